// round 1
// baseline (speedup 1.0000x reference)
#include <cuda_runtime.h>

#define BATCH 64
#define IC 512
#define ID 128
#define NC 32
#define DC 32

// ---- device scratch (static; no allocations) ----
__device__ float g_XT[BATCH * ID * IC];   // X transposed: [b][d][i]  (16.8 MB)
__device__ float g_P [BATCH * NC * IC];   // routing logits            (4 MB)
__device__ float g_Y [BATCH * NC * ID];   // Y = sum_i c * x           (1 MB)
__device__ float g_WV[BATCH * NC * ID];   // wv = W @ v                (1 MB)

// ============================================================
// Kernel 0: transpose X[b][i][d] -> XT[b][d][i]
// grid (IC/32, ID/32, B), block (32, 8)
// ============================================================
__global__ void k_transpose(const float* __restrict__ X) {
    __shared__ float t[32][33];
    const int b  = blockIdx.z;
    const int ib = blockIdx.x << 5;
    const int db = blockIdx.y << 5;
    const float* src = X + ((size_t)b * IC + ib) * ID + db;
#pragma unroll
    for (int r = threadIdx.y; r < 32; r += 8)
        t[r][threadIdx.x] = src[r * ID + threadIdx.x];
    __syncthreads();
    float* dst = g_XT + ((size_t)b * ID + db) * IC + ib;
#pragma unroll
    for (int r = threadIdx.y; r < 32; r += 8)
        dst[r * IC + threadIdx.x] = t[threadIdx.x][r];
}

// ============================================================
// Kernel 1: c = softmax_n(P)   (smem, i-major, pad 33)
//           Y[b,n,d] = sum_i c[b,n,i] * x[b,i,d]
// grid (2, B)  [d-tile of 64, batch], block 256
// dynamic smem: IC*33 floats = 67584 B
// ============================================================
__global__ __launch_bounds__(256) void k_softmax_y(
    const float* __restrict__ X,
    const float* __restrict__ B0,
    int use_b0)
{
    extern __shared__ float c_sm[];        // [IC][33]  (c_sm[i*33+n])
    const int b  = blockIdx.y;
    const int d0 = blockIdx.x * 64;

    const float* P  = use_b0 ? B0 : g_P;
    const float* Pb = P + (size_t)b * NC * IC;

    // load logits (coalesced), scatter to i-major smem (stride 33 -> no conflicts)
    for (int t = threadIdx.x; t < NC * IC; t += 256) {
        const int n = t >> 9;          // / IC
        const int i = t & (IC - 1);
        c_sm[i * 33 + n] = Pb[t];
    }
    __syncthreads();

    // softmax over n (32 values) for each i
    for (int i = threadIdx.x; i < IC; i += 256) {
        float* row = c_sm + i * 33;
        float m = row[0];
#pragma unroll
        for (int n = 1; n < NC; n++) m = fmaxf(m, row[n]);
        float s = 0.f;
#pragma unroll
        for (int n = 0; n < NC; n++) {
            float e = __expf(row[n] - m);
            row[n] = e;
            s += e;
        }
        const float r = __fdividef(1.f, s);
#pragma unroll
        for (int n = 0; n < NC; n++) row[n] *= r;
    }
    __syncthreads();

    // GEMM: Y[n][d0 .. d0+63], register tile 2n x 4d per thread
    const int ng = threadIdx.x >> 4;   // 16 groups -> 2 n each
    const int dg = threadIdx.x & 15;   // 16 groups -> 4 d each
    const int n0 = ng * 2;

    const float4* Xb = (const float4*)(X + (size_t)b * IC * ID + d0) + dg;

    float a00 = 0.f, a01 = 0.f, a02 = 0.f, a03 = 0.f;
    float a10 = 0.f, a11 = 0.f, a12 = 0.f, a13 = 0.f;

#pragma unroll 4
    for (int i = 0; i < IC; i++) {
        const float c0 = c_sm[i * 33 + n0];
        const float c1 = c_sm[i * 33 + n0 + 1];
        const float4 xv = Xb[i * (ID / 4)];
        a00 = fmaf(c0, xv.x, a00);
        a01 = fmaf(c0, xv.y, a01);
        a02 = fmaf(c0, xv.z, a02);
        a03 = fmaf(c0, xv.w, a03);
        a10 = fmaf(c1, xv.x, a10);
        a11 = fmaf(c1, xv.y, a11);
        a12 = fmaf(c1, xv.z, a12);
        a13 = fmaf(c1, xv.w, a13);
    }

    float* Yb = g_Y + ((size_t)b * NC + n0) * ID + d0 + dg * 4;
    *(float4*)(Yb)      = make_float4(a00, a01, a02, a03);
    *(float4*)(Yb + ID) = make_float4(a10, a11, a12, a13);
}

// ============================================================
// Kernel 2: s[b,n,c] = Y[b,n,:] @ W[n][:,c];  v = squash(s)
//           wv[b,n,d] = W[n][d,:] @ v    (skipped on final iter)
// grid (8, NC)  [8-batch group, n], block 256 (8 warps = 8 batches)
// W kept transposed in smem (pad 133) -> conflict-free for both phases
// ============================================================
__global__ __launch_bounds__(256) void k_svwv(
    const float* __restrict__ W,
    float* __restrict__ OUT,
    int final_iter)
{
    __shared__ float WT[NC * 133];   // WT[c*133 + d]
    __shared__ float Ysm[8][ID];
    __shared__ float vsm[8][NC];

    const int n  = blockIdx.y;
    const int b0 = blockIdx.x * 8;

    const float* Wn = W + (size_t)n * ID * NC;   // W[n][d][c]
    for (int t = threadIdx.x; t < ID * NC; t += 256) {
        const int d = t >> 5;
        const int c = t & 31;
        WT[c * 133 + d] = Wn[t];
    }
    for (int t = threadIdx.x; t < 8 * ID; t += 256) {
        const int bb = t >> 7;
        const int d  = t & 127;
        Ysm[bb][d] = g_Y[(((size_t)(b0 + bb)) * NC + n) * ID + d];
    }
    __syncthreads();

    const int c  = threadIdx.x & 31;   // lane = output dim
    const int bb = threadIdx.x >> 5;   // warp = batch within group

    float s = 0.f;
#pragma unroll 8
    for (int d = 0; d < ID; d++)
        s = fmaf(Ysm[bb][d], WT[c * 133 + d], s);

    // squash
    float sn = s * s;
#pragma unroll
    for (int o = 16; o; o >>= 1) sn += __shfl_xor_sync(0xffffffffu, sn, o);
    const float v = s * sn / ((1.f + sn) * (sqrtf(sn) + 1e-8f));

    if (final_iter) {
        OUT[(((size_t)(b0 + bb)) * NC + n) * DC + c] = v;
        return;
    }

    vsm[bb][c] = v;
    __syncthreads();

    // wv[d] = sum_c W[n][d][c] * v[c]; thread handles d = k*32 + lane
    float* wvout = g_WV + (((size_t)(b0 + bb)) * NC + n) * ID;
#pragma unroll
    for (int k = 0; k < 4; k++) {
        const int d = k * 32 + c;
        float acc = 0.f;
#pragma unroll
        for (int cc = 0; cc < NC; cc++)
            acc = fmaf(WT[cc * 133 + d], vsm[bb][cc], acc);
        wvout[d] = acc;
    }
}

// ============================================================
// Kernel 3: uv[b,n,i] = XT[b,:,i] . wv[b,n,:];  P_out = P_in + uv
// grid (4, B)  [i-tile of 128, batch], block 256
// register tile 4n x 4i, XT gives coalesced lane-over-i float4 reads
// ============================================================
__global__ __launch_bounds__(256) void k_uv(
    const float* __restrict__ B0,
    int first)
{
    __shared__ float wv[NC * ID];    // 16 KB
    const int b  = blockIdx.y;
    const int i0 = blockIdx.x * 128;

    for (int t = threadIdx.x; t < NC * ID; t += 256)
        wv[t] = g_WV[(size_t)b * NC * ID + t];
    __syncthreads();

    const int ngr  = threadIdx.x >> 5;   // 0..7 -> 4 n each
    const int lane = threadIdx.x & 31;   // 4 i each (float4)
    const int n0   = ngr * 4;

    const float4* xt = (const float4*)(g_XT + (size_t)b * ID * IC + i0) + lane;

    float acc[4][4];
#pragma unroll
    for (int k = 0; k < 4; k++)
#pragma unroll
        for (int j = 0; j < 4; j++) acc[k][j] = 0.f;

#pragma unroll 2
    for (int d = 0; d < ID; d++) {
        const float4 xv = xt[d * (IC / 4)];
#pragma unroll
        for (int k = 0; k < 4; k++) {
            const float w = wv[(n0 + k) * ID + d];
            acc[k][0] = fmaf(w, xv.x, acc[k][0]);
            acc[k][1] = fmaf(w, xv.y, acc[k][1]);
            acc[k][2] = fmaf(w, xv.z, acc[k][2]);
            acc[k][3] = fmaf(w, xv.w, acc[k][3]);
        }
    }

    const float* pin = first ? B0 : g_P;
#pragma unroll
    for (int k = 0; k < 4; k++) {
        const size_t off = (((size_t)b * NC) + n0 + k) * IC + i0 + lane * 4;
        float4 p = *(const float4*)(pin + off);
        p.x += acc[k][0];
        p.y += acc[k][1];
        p.z += acc[k][2];
        p.w += acc[k][3];
        *(float4*)(g_P + off) = p;
    }
}

// ============================================================
// launch
// ============================================================
extern "C" void kernel_launch(void* const* d_in, const int* in_sizes, int n_in,
                              void* d_out, int out_size) {
    const float *X = nullptr, *W = nullptr, *B0 = nullptr;
    for (int i = 0; i < n_in; i++) {
        if      (in_sizes[i] == BATCH * IC * ID) X  = (const float*)d_in[i];
        else if (in_sizes[i] == NC * ID * DC)    W  = (const float*)d_in[i];
        else if (in_sizes[i] == BATCH * NC * IC) B0 = (const float*)d_in[i];
    }
    float* OUT = (float*)d_out;

    const size_t smem1 = IC * 33 * sizeof(float);   // 67584 B > 48K -> opt-in
    cudaFuncSetAttribute(k_softmax_y,
                         cudaFuncAttributeMaxDynamicSharedMemorySize, (int)smem1);

    k_transpose<<<dim3(16, 4, BATCH), dim3(32, 8)>>>(X);

    // routing iteration 0 (logits = b0)
    k_softmax_y<<<dim3(2, BATCH), 256, smem1>>>(X, B0, 1);
    k_svwv<<<dim3(8, NC), 256>>>(W, OUT, 0);
    k_uv<<<dim3(4, BATCH), 256>>>(B0, 1);

    // routing iteration 1
    k_softmax_y<<<dim3(2, BATCH), 256, smem1>>>(X, B0, 0);
    k_svwv<<<dim3(8, NC), 256>>>(W, OUT, 0);
    k_uv<<<dim3(4, BATCH), 256>>>(B0, 0);

    // final pass: c = softmax(b), s, squash -> output
    k_softmax_y<<<dim3(2, BATCH), 256, smem1>>>(X, B0, 0);
    k_svwv<<<dim3(8, NC), 256>>>(W, OUT, 1);
}

// round 5
// speedup vs baseline: 2.0865x; 2.0865x over previous
#include <cuda_runtime.h>

#define B_  64
#define IC  512
#define ID  128
#define NC  32
#define DC  32
#define IT  4            // i-tiles
#define TI  128          // IC / IT

#define XS_STRIDE 132    // padded row for X tile (16B-aligned, conflict-free both axes)
#define C_STRIDE  36     // padded row for c/logits (16B-aligned for LDS.128)

#define OFF_XS 0
#define OFF_C  (TI * XS_STRIDE)                 // 16896
#define OFF_WV (OFF_C + TI * C_STRIDE)          // 21504
#define SMEM_FLOATS (OFF_WV + NC * ID)          // 25600
#define SMEM_BYTES  (SMEM_FLOATS * 4)           // 102400

// ---- device scratch (static; no allocations) ----
__device__ float g_P [B_ * NC * IC];            // routing logits (4 MB)
__device__ float g_WV[B_ * NC * ID];            // wv = W @ v     (1 MB)
__device__ float g_Yp[IT * B_ * NC * ID];       // partial Y      (4 MB)

// ============================================================
// Fused per-iteration kernel. grid (IT, B_), block 256.
// iter 0: c = softmax(b0 tile)                  -> partial Y
// iter 1: uv = X@wv; b1 = b0+uv (write g_P); softmax -> partial Y
// iter 2: uv = X@wv; b2 = g_P+uv (no write);  softmax -> partial Y
// ============================================================
__global__ __launch_bounds__(256) void k_fused(
    const float* __restrict__ X,
    const float* __restrict__ B0,
    int iter)
{
    extern __shared__ float sm[];
    float* xs  = sm + OFF_XS;   // [TI][XS_STRIDE]
    float* cs  = sm + OFF_C;    // [TI][C_STRIDE]
    float* wvs = sm + OFF_WV;   // [NC][ID]

    const int b    = blockIdx.y;
    const int tt   = blockIdx.x;
    const int i0   = tt * TI;
    const int t    = threadIdx.x;
    const int lane = t & 31;
    const int w    = t >> 5;
    const int n0   = w * 4;     // each warp owns 4 capsule outputs

    // ---- stage X tile: X[b][i0+r][:] -> xs[r][:] (coalesced) ----
    {
        const float4* Xb = (const float4*)(X + ((size_t)b * IC + i0) * ID);
        for (int u = t; u < TI * 32; u += 256) {
            const int r = u >> 5, q = u & 31;
            *(float4*)(xs + r * XS_STRIDE + q * 4) = Xb[r * 32 + q];
        }
    }

    if (iter == 0) {
        // logits tile straight from b0
        const float* Pb = B0 + (size_t)b * NC * IC + i0;
        for (int u = t; u < NC * TI; u += 256) {
            const int n = u >> 7, i = u & 127;
            cs[i * C_STRIDE + n] = Pb[(size_t)n * IC + i];
        }
        __syncthreads();
    } else {
        // stage wv[b]
        for (int u = t; u < NC * ID; u += 256)
            wvs[u] = g_WV[(size_t)b * NC * ID + u];
        __syncthreads();

        // ---- phase 1: uv[n][i] = sum_d xs[i][d] * wv[n][d] ----
        // per thread: 4 n (n0..n0+3) x 4 i (lane + 32*jj)
        float acc[4][4];
#pragma unroll
        for (int k = 0; k < 4; k++)
#pragma unroll
            for (int jj = 0; jj < 4; jj++) acc[k][jj] = 0.f;

#pragma unroll 2
        for (int d = 0; d < ID; d += 4) {
            float4 xq[4];
#pragma unroll
            for (int jj = 0; jj < 4; jj++)
                xq[jj] = *(const float4*)(xs + (lane + 32 * jj) * XS_STRIDE + d);
#pragma unroll
            for (int k = 0; k < 4; k++) {
                const float4 wq = *(const float4*)(wvs + (n0 + k) * ID + d);
#pragma unroll
                for (int jj = 0; jj < 4; jj++) {
                    acc[k][jj] = fmaf(wq.x, xq[jj].x, acc[k][jj]);
                    acc[k][jj] = fmaf(wq.y, xq[jj].y, acc[k][jj]);
                    acc[k][jj] = fmaf(wq.z, xq[jj].z, acc[k][jj]);
                    acc[k][jj] = fmaf(wq.w, xq[jj].w, acc[k][jj]);
                }
            }
        }

        // new logits = prev + uv; write-through if next iteration needs them
        const float* Pprev = (iter == 1) ? B0 : g_P;
#pragma unroll
        for (int k = 0; k < 4; k++)
#pragma unroll
            for (int jj = 0; jj < 4; jj++) {
                const size_t off = ((size_t)b * NC + n0 + k) * IC + i0 + lane + 32 * jj;
                const float nb = Pprev[off] + acc[k][jj];
                if (iter == 1) g_P[off] = nb;
                cs[(lane + 32 * jj) * C_STRIDE + n0 + k] = nb;
            }
        __syncthreads();
    }

    // ---- softmax over n, 2 threads per i-row (halves n-range each) ----
    {
        const int i = t >> 1;
        const int h = (t & 1) << 4;
        float* row = cs + i * C_STRIDE + h;
        float m = row[0];
#pragma unroll
        for (int n = 1; n < 16; n++) m = fmaxf(m, row[n]);
        m = fmaxf(m, __shfl_xor_sync(0xffffffffu, m, 1));
        float s = 0.f;
#pragma unroll
        for (int n = 0; n < 16; n++) {
            const float e = __expf(row[n] - m);
            row[n] = e;
            s += e;
        }
        s += __shfl_xor_sync(0xffffffffu, s, 1);
        const float r = __fdividef(1.f, s);
#pragma unroll
        for (int n = 0; n < 16; n++) row[n] *= r;
    }
    __syncthreads();

    // ---- phase 3: partial Y[n][d] = sum_i c[i][n] * xs[i][d] ----
    // per thread: 4 n (n0..n0+3, broadcast LDS.128) x 4 d (lane*4)
    {
        const int d0 = lane * 4;
        float y[4][4];
#pragma unroll
        for (int k = 0; k < 4; k++)
#pragma unroll
            for (int j = 0; j < 4; j++) y[k][j] = 0.f;

#pragma unroll 2
        for (int i = 0; i < TI; i++) {
            const float4 cq = *(const float4*)(cs + i * C_STRIDE + n0);
            const float4 xv = *(const float4*)(xs + i * XS_STRIDE + d0);
            y[0][0] = fmaf(cq.x, xv.x, y[0][0]);
            y[0][1] = fmaf(cq.x, xv.y, y[0][1]);
            y[0][2] = fmaf(cq.x, xv.z, y[0][2]);
            y[0][3] = fmaf(cq.x, xv.w, y[0][3]);
            y[1][0] = fmaf(cq.y, xv.x, y[1][0]);
            y[1][1] = fmaf(cq.y, xv.y, y[1][1]);
            y[1][2] = fmaf(cq.y, xv.z, y[1][2]);
            y[1][3] = fmaf(cq.y, xv.w, y[1][3]);
            y[2][0] = fmaf(cq.z, xv.x, y[2][0]);
            y[2][1] = fmaf(cq.z, xv.y, y[2][1]);
            y[2][2] = fmaf(cq.z, xv.z, y[2][2]);
            y[2][3] = fmaf(cq.z, xv.w, y[2][3]);
            y[3][0] = fmaf(cq.w, xv.x, y[3][0]);
            y[3][1] = fmaf(cq.w, xv.y, y[3][1]);
            y[3][2] = fmaf(cq.w, xv.z, y[3][2]);
            y[3][3] = fmaf(cq.w, xv.w, y[3][3]);
        }

        float* Yp = g_Yp + (((size_t)tt * B_ + b) * NC + n0) * ID + d0;
#pragma unroll
        for (int k = 0; k < 4; k++)
            *(float4*)(Yp + (size_t)k * ID) = make_float4(y[k][0], y[k][1], y[k][2], y[k][3]);
    }
}

// ============================================================
// Reduce partial Y; s = Y@W; v = squash(s); wv = W@v (or OUT).
// grid (8, NC), block 256: warp = one batch of the 8-group.
// ============================================================
__global__ __launch_bounds__(256) void k_svwv(
    const float* __restrict__ W,
    float* __restrict__ OUT,
    int final_iter)
{
    __shared__ float WT[NC * 133];   // WT[c*133 + d]
    __shared__ float Ysm[8][ID];
    __shared__ float vsm[8][NC];

    const int n  = blockIdx.y;
    const int b0 = blockIdx.x * 8;
    const int t  = threadIdx.x;

    const float* Wn = W + (size_t)n * ID * NC;   // W[n][d][c]
    for (int u = t; u < ID * NC; u += 256) {
        const int d = u >> 5, c = u & 31;
        WT[c * 133 + d] = Wn[u];
    }
    // reduce IT partial tiles
    for (int u = t; u < 8 * ID; u += 256) {
        const int bb = u >> 7, d = u & 127;
        float acc = 0.f;
#pragma unroll
        for (int tt = 0; tt < IT; tt++)
            acc += g_Yp[(((size_t)tt * B_ + b0 + bb) * NC + n) * ID + d];
        Ysm[bb][d] = acc;
    }
    __syncthreads();

    const int c  = t & 31;
    const int bb = t >> 5;

    float s = 0.f;
#pragma unroll 8
    for (int d = 0; d < ID; d++)
        s = fmaf(Ysm[bb][d], WT[c * 133 + d], s);

    float sn = s * s;
#pragma unroll
    for (int o = 16; o; o >>= 1) sn += __shfl_xor_sync(0xffffffffu, sn, o);
    const float v = s * sn / ((1.f + sn) * (sqrtf(sn) + 1e-8f));

    if (final_iter) {
        OUT[(((size_t)(b0 + bb)) * NC + n) * DC + c] = v;
        return;
    }

    vsm[bb][c] = v;
    __syncthreads();

    float* wvout = g_WV + (((size_t)(b0 + bb)) * NC + n) * ID;
#pragma unroll
    for (int k = 0; k < 4; k++) {
        const int d = k * 32 + c;
        float acc = 0.f;
#pragma unroll
        for (int cc = 0; cc < NC; cc++)
            acc = fmaf(WT[cc * 133 + d], vsm[bb][cc], acc);
        wvout[d] = acc;
    }
}

// ============================================================
// launch
// ============================================================
extern "C" void kernel_launch(void* const* d_in, const int* in_sizes, int n_in,
                              void* d_out, int out_size) {
    const float *X = nullptr, *W = nullptr, *B0 = nullptr;
    for (int i = 0; i < n_in; i++) {
        if      (in_sizes[i] == B_ * IC * ID) X  = (const float*)d_in[i];
        else if (in_sizes[i] == NC * ID * DC) W  = (const float*)d_in[i];
        else if (in_sizes[i] == B_ * NC * IC) B0 = (const float*)d_in[i];
    }
    float* OUT = (float*)d_out;

    cudaFuncSetAttribute(k_fused,
                         cudaFuncAttributeMaxDynamicSharedMemorySize, SMEM_BYTES);

    k_fused<<<dim3(IT, B_), 256, SMEM_BYTES>>>(X, B0, 0);
    k_svwv <<<dim3(8, NC), 256>>>(W, OUT, 0);
    k_fused<<<dim3(IT, B_), 256, SMEM_BYTES>>>(X, B0, 1);
    k_svwv <<<dim3(8, NC), 256>>>(W, OUT, 0);
    k_fused<<<dim3(IT, B_), 256, SMEM_BYTES>>>(X, B0, 2);
    k_svwv <<<dim3(8, NC), 256>>>(W, OUT, 1);
}